// round 4
// baseline (speedup 1.0000x reference)
#include <cuda_runtime.h>

#define KC    9
#define TPB   256
#define ROWS  4
#define TILE  (TPB * ROWS)   // 1024 rows per block

__device__ float         g_partials[65536];
__device__ unsigned int  g_counter = 0;

__device__ __forceinline__ float warp_reduce(float v) {
#pragma unroll
    for (int o = 16; o; o >>= 1) v += __shfl_xor_sync(0xffffffffu, v, o);
    return v;
}

__global__ void __launch_bounds__(TPB)
ordinal_loss_fused(const float* __restrict__ logits,
                   const int*   __restrict__ y,
                   float*       __restrict__ out,
                   int B, int nblocks) {
    __shared__ float  sl[TILE * KC];          // 36864 B logits staging
    __shared__ float4 tab[KC * KC];           // per-(y,k): {tailw, farmask, -cdf_true, 0}
    __shared__ float  ws[TPB / 32];
    __shared__ bool   s_last;

    // ---- build the (y,k) table: replaces all integer compare chains ----
    if (threadIdx.x < KC * KC) {
        const int yy = threadIdx.x / KC;
        const int k  = threadIdx.x - yy * KC;
        const int ad = (k > yy) ? (k - yy) : (yy - k);
        const float f1 = (float)(ad - 1);
        tab[threadIdx.x] = make_float4(
            (ad > 1) ? f1 * f1 * f1 : 0.0f,   // tail weight (|k-y|-1)^3
            (ad > 1) ? 1.0f : 0.0f,           // far mask
            (k <= yy) ? -1.0f : 0.0f,         // -cdf_true
            0.0f);
    }

    const int row0  = blockIdx.x * TILE;
    const int nrows = min(TILE, B - row0);

    // ---- stage logits into smem (coalesced 16B streaming loads) ----
    if (nrows == TILE) {
        const float4* src = reinterpret_cast<const float4*>(logits + (size_t)row0 * KC);
        float4*       dst = reinterpret_cast<float4*>(sl);
#pragma unroll
        for (int j = 0; j < TILE * KC / 4 / TPB; j++)
            dst[threadIdx.x + j * TPB] = __ldcs(&src[threadIdx.x + j * TPB]);
    } else {
        for (int j = threadIdx.x; j < nrows * KC; j += TPB)
            sl[j] = logits[(size_t)row0 * KC + j];
    }
    __syncthreads();

    float contrib = 0.0f;

#pragma unroll
    for (int j = 0; j < ROWS; j++) {
        const int r = threadIdx.x + j * TPB;             // strided: smem conflict-free
        if (r < nrows) {
            const int yy   = y[row0 + r];
            const int base = r * KC;

            // exp pass with fused running-cdf (Z = cdf[KC-1])
            float e[KC], cdf[KC];
            float run = 0.0f;
#pragma unroll
            for (int k = 0; k < KC; k++) {
                e[k] = __expf(sl[base + k]);
                run += e[k];
                cdf[k] = run;
            }
            const float Z  = run;
            const float rZ = __fdividef(1.0f, Z);

            // target / neighbor probs via direct (dynamic) smem loads
            const float ly = sl[base + yy];
            const int   il = base + ((yy > 0)      ? yy - 1 : 0);
            const int   ir = base + ((yy < KC - 1) ? yy + 1 : KC - 1);
            const float pl_e = (yy > 0)      ? __expf(sl[il]) : 0.0f;
            const float pr_e = (yy < KC - 1) ? __expf(sl[ir]) : 0.0f;
            const float py_e = __expf(ly);

            const float nll = __logf(Z) - ly;

            // table-driven pass: pure FMA-pipe work
            const float4* trow = &tab[yy * KC];
            float far_e = 0.0f, tail_e = 0.0f, emd2 = 0.0f;
#pragma unroll
            for (int k = 0; k < KC; k++) {
                const float4 tb = trow[k];
                tail_e = fmaf(e[k], tb.x, tail_e);
                far_e  = fmaxf(far_e, e[k] * tb.y);
                const float df = fmaf(cdf[k], rZ, tb.z);
                const float w  = (k == 0) ? 3.0f/95.0f : (k == 1) ? 7.0f/95.0f
                               : (k == KC-1) ? 25.0f/95.0f : 10.0f/95.0f;
                emd2 = fmaf(df * df, w, emd2);
            }

            const float py   = py_e * rZ;
            const float far_margin = fmaxf(fmaf(far_e, rZ, -(py - 0.15f)), 0.0f);
            const float local_peak = fmaxf(fmaf(fmaxf(pl_e, pr_e), rZ, -(py - 0.35f)), 0.0f);
            const float tail = tail_e * rZ;

            contrib += nll * 0.45511961331341866f        // 1/ln(9)
                     + 0.4f * (7.0f * far_margin + 9.0f * tail
                             + 12.0f * local_peak + 1.2f * emd2);
        }
    }

    // ---- block reduction ----
    contrib = warp_reduce(contrib);
    if ((threadIdx.x & 31) == 0) ws[threadIdx.x >> 5] = contrib;
    __syncthreads();
    if (threadIdx.x < 32) {
        float v = (threadIdx.x < TPB / 32) ? ws[threadIdx.x] : 0.0f;
        v = warp_reduce(v);
        if (threadIdx.x == 0) {
            g_partials[blockIdx.x] = v;
            __threadfence();
            unsigned int t = atomicAdd(&g_counter, 1u);
            s_last = (t == (unsigned int)(nblocks - 1));
        }
    }
    __syncthreads();

    // ---- last arriving block: deterministic fixed-order final sum ----
    if (s_last) {
        float v = 0.0f;
        for (int i = threadIdx.x; i < nblocks; i += TPB) v += g_partials[i];
        v = warp_reduce(v);
        if ((threadIdx.x & 31) == 0) ws[threadIdx.x >> 5] = v;
        __syncthreads();
        if (threadIdx.x < 32) {
            float t = (threadIdx.x < TPB / 32) ? ws[threadIdx.x] : 0.0f;
            t = warp_reduce(t);
            if (threadIdx.x == 0) {
                out[0] = t / (float)B;
                g_counter = 0;                 // re-arm for next graph replay
            }
        }
    }
}

extern "C" void kernel_launch(void* const* d_in, const int* in_sizes, int n_in,
                              void* d_out, int out_size) {
    const float* logits = (const float*)d_in[0];
    const int*   y      = (const int*)d_in[1];
    const int    B      = in_sizes[1];

    const int nblocks = (B + TILE - 1) / TILE;     // 4096 for B = 4,194,304

    ordinal_loss_fused<<<nblocks, TPB>>>(logits, y, (float*)d_out, B, nblocks);
}

// round 5
// speedup vs baseline: 1.7312x; 1.7312x over previous
#include <cuda_runtime.h>

#define KC    9
#define TPB   256
#define ROWS  4
#define TILE  (TPB * ROWS)   // 1024 rows per block

__device__ float         g_partials[65536];
__device__ unsigned int  g_counter = 0;

__device__ __forceinline__ float warp_reduce(float v) {
#pragma unroll
    for (int o = 16; o; o >>= 1) v += __shfl_xor_sync(0xffffffffu, v, o);
    return v;
}

__global__ void __launch_bounds__(TPB)
ordinal_loss_fused(const float* __restrict__ logits,
                   const int*   __restrict__ y,
                   float*       __restrict__ out,
                   int B, int nblocks) {
    __shared__ float sl[TILE * KC];          // 36864 B staging
    __shared__ float ws[TPB / 32];
    __shared__ bool  s_last;

    const int row0  = blockIdx.x * TILE;
    const int nrows = min(TILE, B - row0);

    // ---- stage logits into smem (coalesced 16B streaming loads) ----
    if (nrows == TILE) {
        const float4* src = reinterpret_cast<const float4*>(logits + (size_t)row0 * KC);
        float4*       dst = reinterpret_cast<float4*>(sl);
#pragma unroll
        for (int j = 0; j < TILE * KC / 4 / TPB; j++)
            dst[threadIdx.x + j * TPB] = __ldcs(&src[threadIdx.x + j * TPB]);
    } else {
        for (int j = threadIdx.x; j < nrows * KC; j += TPB)
            sl[j] = logits[(size_t)row0 * KC + j];
    }
    __syncthreads();

    float contrib = 0.0f;

#pragma unroll
    for (int j = 0; j < ROWS; j++) {
        const int r = threadIdx.x + j * TPB;             // strided: smem conflict-free
        if (r < nrows) {
            const int   yy   = y[row0 + r];
            const int   base = r * KC;
            const float yf   = (float)yy;                // single I2F per row

            // exp + running cdf (Z = cdf[last])
            float e[KC], cdf[KC];
            float run = 0.0f;
#pragma unroll
            for (int k = 0; k < KC; k++) {
                e[k] = __expf(sl[base + k]);
                run += e[k];
                cdf[k] = run;
            }
            const float Z  = run;
            const float rZ = __fdividef(1.0f, Z);

            // target / neighbor probs via direct dynamic smem loads (only 3)
            const float ly   = sl[base + yy];
            const float py_e = __expf(ly);
            const float pl_e = (yy > 0)      ? __expf(sl[base + yy - 1]) : 0.0f;
            const float pr_e = (yy < KC - 1) ? __expf(sl[base + yy + 1]) : 0.0f;

            const float nll = __logf(Z) - ly;

            // select-free FMA-pipe pass:
            //   f1 = max(||k-y|| - 1, 0)        -> tail base, far via min(f1,1)
            //   t  = saturate(y - k + 1)        -> exact cdf_true indicator
            float far_e = 0.0f, tail_e = 0.0f, emd2 = 0.0f;
#pragma unroll
            for (int k = 0; k < KC; k++) {
                const float ad = fabsf((float)k - yf);
                const float f1 = fmaxf(ad - 1.0f, 0.0f);
                const float g  = fminf(f1, 1.0f);
                tail_e = fmaf(e[k], f1 * f1 * f1, tail_e);
                far_e  = fmaxf(far_e, e[k] * g);

                const float t  = __saturatef(yf - (float)(k - 1));
                const float df = fmaf(cdf[k], rZ, -t);
                const float w  = (k == 0) ? 3.0f/95.0f : (k == 1) ? 7.0f/95.0f
                               : (k == KC-1) ? 25.0f/95.0f : 10.0f/95.0f;
                emd2 = fmaf(df * df, w, emd2);
            }

            const float py = py_e * rZ;
            const float far_margin = fmaxf(fmaf(far_e, rZ, -(py - 0.15f)), 0.0f);
            const float local_peak = fmaxf(fmaf(fmaxf(pl_e, pr_e), rZ, -(py - 0.35f)), 0.0f);
            const float tail = tail_e * rZ;

            contrib += nll * 0.45511961331341866f        // 1/ln(9)
                     + 0.4f * (7.0f * far_margin + 9.0f * tail
                             + 12.0f * local_peak + 1.2f * emd2);
        }
    }

    // ---- block reduction ----
    contrib = warp_reduce(contrib);
    if ((threadIdx.x & 31) == 0) ws[threadIdx.x >> 5] = contrib;
    __syncthreads();
    if (threadIdx.x < 32) {
        float v = (threadIdx.x < TPB / 32) ? ws[threadIdx.x] : 0.0f;
        v = warp_reduce(v);
        if (threadIdx.x == 0) {
            g_partials[blockIdx.x] = v;
            __threadfence();
            unsigned int t = atomicAdd(&g_counter, 1u);
            s_last = (t == (unsigned int)(nblocks - 1));
        }
    }
    __syncthreads();

    // ---- last arriving block: deterministic fixed-order final sum ----
    if (s_last) {
        float v = 0.0f;
        for (int i = threadIdx.x; i < nblocks; i += TPB) v += g_partials[i];
        v = warp_reduce(v);
        if ((threadIdx.x & 31) == 0) ws[threadIdx.x >> 5] = v;
        __syncthreads();
        if (threadIdx.x < 32) {
            float t = (threadIdx.x < TPB / 32) ? ws[threadIdx.x] : 0.0f;
            t = warp_reduce(t);
            if (threadIdx.x == 0) {
                out[0] = t / (float)B;
                g_counter = 0;                 // re-arm for next graph replay
            }
        }
    }
}

extern "C" void kernel_launch(void* const* d_in, const int* in_sizes, int n_in,
                              void* d_out, int out_size) {
    const float* logits = (const float*)d_in[0];
    const int*   y      = (const int*)d_in[1];
    const int    B      = in_sizes[1];

    const int nblocks = (B + TILE - 1) / TILE;     // 4096 for B = 4,194,304

    ordinal_loss_fused<<<nblocks, TPB>>>(logits, y, (float*)d_out, B, nblocks);
}